// round 11
// baseline (speedup 1.0000x reference)
#include <cuda_runtime.h>
#include <cstdint>
#include <cstddef>

// Correlation: out[b, ix*21+iy, h, w] = sum_c f1[b,c,h,w] * f2[b,c,h+2ix-20, w+2iy-20]
// B=4, C=128, H=96, W=192, D=20, stride 2 -> 441 offsets.
//
// Parity FIR: out[u][j] += f1[u] * f2p[u+j-10], smem slot s = u+j in [10,105].
// R11 = R2's best-ratio thread (FULL 21 taps, Ut=4, 84 accs -> 12 FMA/LDS.128)
// + multi-CTA residency: 192 threads (4q x 2p x 24t), launch_bounds(192,3)
// -> 3 CTAs/SM, independent barriers destagger so staging stalls are covered
// cross-CTA. Immediate LDG->STS staging (no prefetch regs), 64-bit pointers,
// one pointer add per chunk. ix = 4*ixg + q; ix 21..23 are dummy (not stored).
// Layout per c (1200 floats): [f1 p0|p1 (120 each)] [qq=0..3: p0|p1 (120 each)].

#define NTHR   192
#define Q      4
#define CC     2
#define CROWF  1200                      // floats per channel block
#define BUF    (CC * CROWF)              // 2400 floats per buffer
#define NSEG   (CC * 5 * 48)             // 480 float4 segments per chunk
#define NL     3                         // ceil(480/192)
#define CH_STRIDE 18432                  // 96*192 floats per channel

__global__ void __launch_bounds__(NTHR, 3)
corr_kernel(const float* __restrict__ f1, const float* __restrict__ f2,
            float* __restrict__ out)
{
    extern __shared__ float smem[];

    const int h   = blockIdx.x;   // 0..95
    const int b   = blockIdx.y;   // 0..3
    const int ixg = blockIdx.z;   // 0..5 : ix quad {4*ixg .. 4*ixg+3}
    const int tid = threadIdx.x;

    const int q  = tid / 48;           // 0..3 : ix within quad
    const int r1 = tid % 48;
    const int p  = r1 / 24;            // parity of w
    const int t  = r1 % 24;            // u-tile
    const int u0 = 4 * t;
    const int ix = 4 * ixg + q;        // 21..23 dummy (computed, never stored)
    const int h2base = h + 8 * ixg - 20;

    // zero both buffers once: pad slots / OOB rows stay zero forever
    for (int i = tid; i < 2 * BUF; i += NTHR) smem[i] = 0.0f;

    // ---- one-time staging precompute: NL (64-bit gptr, smem float offset) ----
    const float4* gp[NL];
    int so[NL];                         // float offset in buffer; -1 = invalid
    #pragma unroll
    for (int i = 0; i < NL; i++) {
        so[i] = -1;
        gp[i] = (const float4*)f1;
        int idx = tid + i * NTHR;
        if (idx < NSEG) {
            int c   = idx / 240;
            int rr  = idx - c * 240;
            int row = rr / 48;          // 0 = f1, 1..4 = f2 (qq = row-1)
            int op  = rr - row * 48;    // 16B segment in source row
            if (row == 0) {
                gp[i] = (const float4*)(f1 + ((size_t)(b*128 + c)*96 + h)*192 + 4*op);
                so[i] = c * CROWF + 2 * op;                   // even u=2op; odd +120
            } else {
                int qq = row - 1;
                int h2 = h2base + 2 * qq;
                if ((unsigned)h2 < 96u) {
                    gp[i] = (const float4*)(f2 + ((size_t)(b*128 + c)*96 + h2)*192 + 4*op);
                    so[i] = c * CROWF + 240 + qq * 240 + (2 * op + 10);   // s=2op+10
                }
            }
        }
    }

    auto stage = [&](float* dst) {
        float4 tv[NL];
        #pragma unroll
        for (int i = 0; i < NL; i++)
            if (so[i] >= 0) {
                tv[i] = *gp[i];
                gp[i] += CC * CH_STRIDE / 4;
            }
        #pragma unroll
        for (int i = 0; i < NL; i++)
            if (so[i] >= 0) {
                // float4 at w=4op: even-parity floats (x,z), odd (y,w)
                *(float2*)(dst + so[i])       = make_float2(tv[i].x, tv[i].z);
                *(float2*)(dst + so[i] + 120) = make_float2(tv[i].y, tv[i].w);
            }
    };

    float acc[84];                     // [k 0..3][j 0..20]
    #pragma unroll
    for (int i = 0; i < 84; i++) acc[i] = 0.0f;

    __syncthreads();                   // zeros visible
    stage(smem);                       // chunk 0 -> buffer 0
    __syncthreads();

    const float* vb = smem + p * 120 + u0;                       // f1 parity row
    const float* wb = smem + 240 + q * 240 + p * 120 + u0;       // window base

    const int NCHUNK = 128 / CC;       // 64
    #pragma unroll 1
    for (int cc = 0; cc < NCHUNK; cc++) {
        const int curo = (cc & 1) * BUF;

        if (cc + 1 < NCHUNK)
            stage(smem + ((cc + 1) & 1) * BUF);   // covered by co-resident CTAs

        #pragma unroll
        for (int c = 0; c < CC; c++) {
            float4 V = *(const float4*)(vb + curo + c * CROWF);
            const float4* wp = (const float4*)(wb + curo + c * CROWF);
            float a[4] = {V.x, V.y, V.z, V.w};
            // slots u0..u0+23 in 6 float4s, consumed immediately (low pressure)
            #pragma unroll
            for (int wi = 0; wi < 6; wi++) {
                float4 W = wp[wi];
                float wf[4] = {W.x, W.y, W.z, W.w};
                #pragma unroll
                for (int e = 0; e < 4; e++) {
                    #pragma unroll
                    for (int k = 0; k < 4; k++) {
                        constexpr int dummy = 0; (void)dummy;
                        int j = 4 * wi + e - k;          // compile-time
                        if (j >= 0 && j < 21)
                            acc[k * 21 + j] = fmaf(a[k], wf[e], acc[k * 21 + j]);
                    }
                }
            }
        }
        __syncthreads();
    }

    // store (skip dummy ix): out[((b*441 + ix*21 + j)*96 + h)*192 + 2*(u0+k)+p]
    if (ix < 21) {
        size_t obase = (((size_t)b * 441 + (size_t)ix * 21) * 96 + h) * 192
                       + 2 * u0 + p;
        #pragma unroll
        for (int j = 0; j < 21; j++) {
            size_t ob = obase + (size_t)j * CH_STRIDE;
            #pragma unroll
            for (int k = 0; k < 4; k++)
                out[ob + 2 * k] = acc[k * 21 + j];
        }
    }
}

extern "C" void kernel_launch(void* const* d_in, const int* in_sizes, int n_in,
                              void* d_out, int out_size)
{
    const float* f1 = (const float*)d_in[0];
    const float* f2 = (const float*)d_in[1];
    float* out = (float*)d_out;

    size_t smem_bytes = (size_t)2 * BUF * sizeof(float);   // 19200 B
    cudaFuncSetAttribute(corr_kernel, cudaFuncAttributeMaxDynamicSharedMemorySize,
                         (int)smem_bytes);

    dim3 grid(96, 4, 6);   // (h, b, ix-quad)
    corr_kernel<<<grid, NTHR, smem_bytes>>>(f1, f2, out);
}

// round 12
// speedup vs baseline: 2.5268x; 2.5268x over previous
#include <cuda_runtime.h>
#include <cstdint>
#include <cstddef>

// Correlation: out[b, ix*21+iy, h, w] = sum_c f1[b,c,h,w] * f2[b,c,h+2ix-20, w+2iy-20]
// B=4, C=128, H=96, W=192, D=20, stride 2 -> 441 offsets.
//
// Parity FIR: out[u][j] += f1[u] * f2p[u+j-10], smem slot s = u+j in [10,105].
// Thread = FULL 21 taps, Ut=4 (84 accs, 12 FMA per LDS.128 - best ratio).
// R12: registers first. launch_bounds(192,2) -> cap 168, no spills (R11's
// 112-reg cap spilled the acc array -> 2.6x blowup). 2 CTAs/SM, independent
// barriers. Block = 2 h-rows x 2 ix (grid 48x4x11, only ix=21 dummy, 4.5%):
// the CTA's 4 f2 window rows are consecutive (h0+4*ixg-20+{0..3}, indexed by
// h'+2q). Staging: 64-bit ptrs, one add/chunk, immediate LDG->STS, NL=3 exact.
// Layout per c (1440 floats): f1[h'(2)][p(2)][120] then f2[wr(4)][p(2)][120].

#define NTHR   192
#define CC     2
#define CROWF  1440                      // floats per channel block
#define BUF    (CC * CROWF)              // 2880 floats per buffer
#define NSEG   (CC * 6 * 48)             // 576 float4 segments per chunk
#define NL     3                         // 576 / 192 exact
#define CH_STRIDE 18432                  // 96*192 floats per channel

__global__ void __launch_bounds__(NTHR, 2)
corr_kernel(const float* __restrict__ f1, const float* __restrict__ f2,
            float* __restrict__ out)
{
    extern __shared__ float smem[];

    const int h0  = 2 * blockIdx.x;  // h pair {h0, h0+1}
    const int b   = blockIdx.y;      // 0..3
    const int ixg = blockIdx.z;      // 0..10 : ix pair {2*ixg, 2*ixg+1}
    const int tid = threadIdx.x;

    const int hh = tid / 96;           // 0..1 : h = h0 + hh
    const int r0 = tid % 96;
    const int q  = r0 / 48;            // 0..1 : ix = 2*ixg + q
    const int r1 = r0 % 48;
    const int p  = r1 / 24;            // parity of w
    const int t  = r1 % 24;            // u-tile
    const int u0 = 4 * t;
    const int ix = 2 * ixg + q;        // ix == 21 -> dummy (never stored)
    const int h2base = h0 + 4 * ixg - 20;   // window row wr=h'+2q -> h2base+wr

    // zero both buffers once: pad slots / OOB rows stay zero forever
    for (int i = tid; i < 2 * BUF; i += NTHR) smem[i] = 0.0f;

    // ---- one-time staging precompute: NL (64-bit gptr, smem float offset) ----
    const float4* gp[NL];
    int so[NL];                         // float offset in buffer; -1 = invalid
    #pragma unroll
    for (int i = 0; i < NL; i++) {
        so[i] = -1;
        gp[i] = (const float4*)f1;
        int idx = tid + i * NTHR;       // < NSEG always (576 = 3*192)
        int c   = idx / 288;
        int rr  = idx - c * 288;
        int row = rr / 48;              // 0..1 = f1 rows, 2..5 = f2 window rows
        int op  = rr - row * 48;        // 16B segment in source row
        if (row < 2) {
            gp[i] = (const float4*)(f1 + ((size_t)(b*128 + c)*96 + (h0+row))*192 + 4*op);
            so[i] = c * CROWF + row * 240 + 2 * op;           // even; odd +120
        } else {
            int wr = row - 2;
            int h2 = h2base + wr;
            if ((unsigned)h2 < 96u) {
                gp[i] = (const float4*)(f2 + ((size_t)(b*128 + c)*96 + h2)*192 + 4*op);
                so[i] = c * CROWF + 480 + wr * 240 + (2 * op + 10);   // s=2op+10
            }
        }
    }

    auto stage = [&](float* dst) {
        float4 tv[NL];
        #pragma unroll
        for (int i = 0; i < NL; i++)
            if (so[i] >= 0) {
                tv[i] = *gp[i];
                gp[i] += CC * CH_STRIDE / 4;
            }
        #pragma unroll
        for (int i = 0; i < NL; i++)
            if (so[i] >= 0) {
                // float4 at w=4op: even-parity floats (x,z), odd (y,w)
                *(float2*)(dst + so[i])       = make_float2(tv[i].x, tv[i].z);
                *(float2*)(dst + so[i] + 120) = make_float2(tv[i].y, tv[i].w);
            }
    };

    float acc[84];                     // [k 0..3][j 0..20]
    #pragma unroll
    for (int i = 0; i < 84; i++) acc[i] = 0.0f;

    __syncthreads();                   // zeros visible
    stage(smem);                       // chunk 0 -> buffer 0
    __syncthreads();

    const float* vb = smem + hh * 240 + p * 120 + u0;                  // f1 row
    const float* wb = smem + 480 + (hh + 2 * q) * 240 + p * 120 + u0;  // window

    const int NCHUNK = 128 / CC;       // 64
    #pragma unroll 1
    for (int cc = 0; cc < NCHUNK; cc++) {
        const int curo = (cc & 1) * BUF;

        if (cc + 1 < NCHUNK)
            stage(smem + ((cc + 1) & 1) * BUF);   // covered by co-resident CTA

        #pragma unroll
        for (int c = 0; c < CC; c++) {
            float4 V = *(const float4*)(vb + curo + c * CROWF);
            const float4* wp = (const float4*)(wb + curo + c * CROWF);
            float a[4] = {V.x, V.y, V.z, V.w};
            #pragma unroll
            for (int wi = 0; wi < 6; wi++) {       // slots u0..u0+23
                float4 W = wp[wi];
                float wf[4] = {W.x, W.y, W.z, W.w};
                #pragma unroll
                for (int e = 0; e < 4; e++) {
                    #pragma unroll
                    for (int k = 0; k < 4; k++) {
                        int j = 4 * wi + e - k;     // compile-time
                        if (j >= 0 && j < 21)
                            acc[k * 21 + j] = fmaf(a[k], wf[e], acc[k * 21 + j]);
                    }
                }
            }
        }
        __syncthreads();
    }

    // store: out[((b*441 + ix*21 + j)*96 + h0+hh)*192 + 2*(u0+k)+p]
    if (ix < 21) {
        size_t obase = (((size_t)b * 441 + (size_t)ix * 21) * 96 + (h0 + hh)) * 192
                       + 2 * u0 + p;
        #pragma unroll
        for (int j = 0; j < 21; j++) {
            size_t ob = obase + (size_t)j * CH_STRIDE;
            #pragma unroll
            for (int k = 0; k < 4; k++)
                out[ob + 2 * k] = acc[k * 21 + j];
        }
    }
}

extern "C" void kernel_launch(void* const* d_in, const int* in_sizes, int n_in,
                              void* d_out, int out_size)
{
    const float* f1 = (const float*)d_in[0];
    const float* f2 = (const float*)d_in[1];
    float* out = (float*)d_out;

    size_t smem_bytes = (size_t)2 * BUF * sizeof(float);   // 23040 B
    cudaFuncSetAttribute(corr_kernel, cudaFuncAttributeMaxDynamicSharedMemorySize,
                         (int)smem_bytes);

    dim3 grid(48, 4, 11);   // (h-pair, b, ix-pair)
    corr_kernel<<<grid, NTHR, smem_bytes>>>(f1, f2, out);
}